// round 1
// baseline (speedup 1.0000x reference)
#include <cuda_runtime.h>
#include <mma.h>
#include <math.h>

using namespace nvcuda;

#define GRIDN 16
#define NN 256
#define DD 64
#define BB 4096
#define FF 512
#define HH 16384
#define CC 1000
#define CPAD 1024

// ---------------- scratch (static device globals: allocation-guard safe) ----
__device__ float g_nodes[(size_t)BB * HH];    // 256 MB
__device__ float g_xclean[(size_t)BB * HH];   // 256 MB
__device__ float g_logits[(size_t)BB * CPAD]; // 16 MB (padded readout)
__device__ float g_adjw[NN * 4];
__device__ int   g_adjn[NN * 4];
__device__ float g_K[4 * DD];

__device__ __forceinline__ float sigmoidf_(float x) { return 1.0f / (1.0f + expf(-x)); }
__device__ __forceinline__ float clip3(float x) { return fminf(fmaxf(x, -3.0f), 3.0f); }

// ---------------- prep: adjacency rows + K = basis @ k_w^T + k_b -----------
__global__ void prep_kernel(const float* __restrict__ adjw,
                            const float* __restrict__ k_w,
                            const float* __restrict__ k_b,
                            const float* __restrict__ basis)
{
    int t = threadIdx.x;  // 256 threads, t = node index
    int r = t >> 4, c = t & 15;
    int nb[4]; int cnt = 0;
    if (r > 0)         nb[cnt++] = t - GRIDN;
    if (r < GRIDN - 1) nb[cnt++] = t + GRIDN;
    if (c > 0)         nb[cnt++] = t - 1;
    if (c < GRIDN - 1) nb[cnt++] = t + 1;

    float w[4] = {0.f, 0.f, 0.f, 0.f};
    float deg = 0.f;
    for (int j = 0; j < cnt; j++) { w[j] = sigmoidf_(adjw[t * NN + nb[j]]); deg += w[j]; }
    deg = fmaxf(deg, 1e-6f);
    int over = 0;
    for (int j = 0; j < cnt; j++) { w[j] /= deg; if (w[j] > 0.1f) over++; }
    if (over < 1) w[0] = fmaxf(w[0], 0.5f);  // survival boost on first neighbor
    for (int j = 0; j < 4; j++) {
        g_adjw[t * 4 + j] = (j < cnt) ? w[j] : 0.f;
        g_adjn[t * 4 + j] = (j < cnt) ? nb[j] : t;
    }

    // K[4,64] exact fp32
    int kr = t >> 6, kc = t & 63;
    float acc = k_b[kc];
    for (int d = 0; d < DD; d++) acc += basis[kr * DD + d] * k_w[kc * DD + d];
    g_K[kr * DD + kc] = acc;
}

// ---------------- generic NT GEMM: C[M,ldc] = A[M,K] * B[Nvalid,K]^T (tf32) -
#define BM 128
#define BN 128
#define BKK 32
#define LDS_ (BKK + 4)

__global__ __launch_bounds__(256) void gemm_nt_tf32(
    const float* __restrict__ A, const float* __restrict__ B, float* __restrict__ C,
    int M, int Nvalid, int K, int ldc)
{
    __shared__ float As[BM * LDS_];
    __shared__ float Bs[BN * LDS_];
    int t = threadIdx.x;
    int m0 = blockIdx.y * BM;
    int n0 = blockIdx.x * BN;
    int w = t >> 5;
    int wm = w & 1;   // 2 warp rows   (64 rows each)
    int wn = w >> 1;  // 4 warp cols   (32 cols each)

    wmma::fragment<wmma::accumulator, 16, 16, 8, float> acc[4][2];
    #pragma unroll
    for (int i = 0; i < 4; i++)
        #pragma unroll
        for (int j = 0; j < 2; j++) wmma::fill_fragment(acc[i][j], 0.0f);

    for (int k0 = 0; k0 < K; k0 += BKK) {
        #pragma unroll
        for (int i = 0; i < 4; i++) {
            int id = t + i * 256;          // 0..1023
            int row = id >> 3, c4 = id & 7;
            float4 av = ((const float4*)(A + (size_t)(m0 + row) * K + k0))[c4];
            float* d = &As[row * LDS_ + c4 * 4];
            d[0] = wmma::__float_to_tf32(av.x); d[1] = wmma::__float_to_tf32(av.y);
            d[2] = wmma::__float_to_tf32(av.z); d[3] = wmma::__float_to_tf32(av.w);
            int hrow = n0 + row;
            float4 bv = make_float4(0.f, 0.f, 0.f, 0.f);
            if (hrow < Nvalid) bv = ((const float4*)(B + (size_t)hrow * K + k0))[c4];
            float* e = &Bs[row * LDS_ + c4 * 4];
            e[0] = wmma::__float_to_tf32(bv.x); e[1] = wmma::__float_to_tf32(bv.y);
            e[2] = wmma::__float_to_tf32(bv.z); e[3] = wmma::__float_to_tf32(bv.w);
        }
        __syncthreads();
        #pragma unroll
        for (int kk = 0; kk < BKK / 8; kk++) {
            wmma::fragment<wmma::matrix_a, 16, 16, 8, wmma::precision::tf32, wmma::row_major> af[4];
            wmma::fragment<wmma::matrix_b, 16, 16, 8, wmma::precision::tf32, wmma::col_major> bf[2];
            #pragma unroll
            for (int i = 0; i < 4; i++)
                wmma::load_matrix_sync(af[i], &As[(wm * 64 + i * 16) * LDS_ + kk * 8], LDS_);
            #pragma unroll
            for (int j = 0; j < 2; j++)
                wmma::load_matrix_sync(bf[j], &Bs[(wn * 32 + j * 16) * LDS_ + kk * 8], LDS_);
            #pragma unroll
            for (int i = 0; i < 4; i++)
                #pragma unroll
                for (int j = 0; j < 2; j++)
                    wmma::mma_sync(acc[i][j], af[i], bf[j], acc[i][j]);
        }
        __syncthreads();
    }
    #pragma unroll
    for (int i = 0; i < 4; i++)
        #pragma unroll
        for (int j = 0; j < 2; j++)
            wmma::store_matrix_sync(C + (size_t)(m0 + wm * 64 + i * 16) * ldc + n0 + wn * 32 + j * 16,
                                    acc[i][j], ldc, wmma::mem_row_major);
}

// ---------------- fused middle: one CTA per batch element -------------------
#define MLD 68
constexpr int MID_SMEM_FLOATS = 256 * MLD * 2 + 64 * MLD * 3 + 256 + 1024 + 256 + 256 + 64 + 64 + 1024;
constexpr int MID_SMEM_BYTES  = MID_SMEM_FLOATS * 4;   // ~203 KB

__global__ __launch_bounds__(256) void middle_kernel(
    const float* __restrict__ b_in, const float* __restrict__ V_slow,
    const float* __restrict__ sem_mem, const float* __restrict__ mix_w,
    const float* __restrict__ mix_b, const float* __restrict__ basis,
    const float* __restrict__ q_w, const float* __restrict__ q_b)
{
    extern __shared__ float smem_[];
    float* sA   = smem_;               // 256*68  working buffer A
    float* sB   = sA + 256 * MLD;      // 256*68  working buffer B
    float* sV   = sB + 256 * MLD;      // 64*68   V_slow (tf32)
    float* sS   = sV + 64 * MLD;       // 64*68   sem_mem (tf32)
    float* sQm  = sS + 64 * MLD;       // 64*68   q_w (tf32)
    float* smix = sQm + 64 * MLD;      // 256
    float* sw4  = smix + 256;          // 256*4
    float* sKb  = sw4 + 1024;          // 4*64
    float* sBas = sKb + 256;           // 4*64
    float* sqb  = sBas + 256;          // 64
    float* smw  = sqb + 64;            // 64
    int*   sn4  = (int*)(smw + 64);    // 256*4

    int b = blockIdx.x;
    int t = threadIdx.x;

    for (int i = t; i < 64 * 64; i += 256) {
        int r = i >> 6, c2 = i & 63;
        sV[r * MLD + c2]  = wmma::__float_to_tf32(V_slow[i]);
        sS[r * MLD + c2]  = wmma::__float_to_tf32(sem_mem[i]);
        sQm[r * MLD + c2] = wmma::__float_to_tf32(q_w[i]);
    }
    if (t < 64) { sqb[t] = q_b[t]; smw[t] = mix_w[t]; }
    sKb[t]  = g_K[t];      // t covers 0..255 = 4*64
    sBas[t] = basis[t];
    #pragma unroll
    for (int j = 0; j < 4; j++) { sw4[t * 4 + j] = g_adjw[t * 4 + j]; sn4[t * 4 + j] = g_adjn[t * 4 + j]; }

    // nodes + input bias  -> sA (fp32)
    {
        const float4* np_ = (const float4*)(g_nodes + (size_t)b * HH);
        const float4* bp_ = (const float4*)b_in;
        for (int i = t; i < HH / 4; i += 256) {
            float4 v = np_[i], bb = bp_[i];
            int n = i >> 4, d = (i & 15) << 2;
            float* dst = &sA[n * MLD + d];
            dst[0] = v.x + bb.x; dst[1] = v.y + bb.y; dst[2] = v.z + bb.z; dst[3] = v.w + bb.w;
        }
    }
    __syncthreads();

    // sparse message passing: agg -> sB (tf32)
    {
        int n = t;
        float w0 = sw4[n * 4 + 0], w1 = sw4[n * 4 + 1], w2 = sw4[n * 4 + 2], w3 = sw4[n * 4 + 3];
        const float* r0 = &sA[sn4[n * 4 + 0] * MLD];
        const float* r1 = &sA[sn4[n * 4 + 1] * MLD];
        const float* r2 = &sA[sn4[n * 4 + 2] * MLD];
        const float* r3 = &sA[sn4[n * 4 + 3] * MLD];
        float* dst = &sB[n * MLD];
        #pragma unroll
        for (int d = 0; d < DD; d++)
            dst[d] = wmma::__float_to_tf32(w0 * r0[d] + w1 * r1[d] + w2 * r2[d] + w3 * r3[d]);
    }
    __syncthreads();

    int w = t >> 5;
    int r0w = w * 32;   // each of 8 warps owns 32 rows

    typedef wmma::fragment<wmma::matrix_a, 16, 16, 8, wmma::precision::tf32, wmma::row_major> AFrag;
    typedef wmma::fragment<wmma::matrix_b, 16, 16, 8, wmma::precision::tf32, wmma::col_major> BFrag;
    typedef wmma::fragment<wmma::accumulator, 16, 16, 8, float> CFrag;

    // v = clip(agg @ V^T), y_pred = clip(agg @ S^T)
    {
        CFrag vf[2][4], yf[2][4];
        #pragma unroll
        for (int i = 0; i < 2; i++)
            #pragma unroll
            for (int j = 0; j < 4; j++) { wmma::fill_fragment(vf[i][j], 0.f); wmma::fill_fragment(yf[i][j], 0.f); }
        #pragma unroll
        for (int kk = 0; kk < 8; kk++) {
            AFrag af[2]; BFrag bv[4], bs[4];
            #pragma unroll
            for (int i = 0; i < 2; i++) wmma::load_matrix_sync(af[i], &sB[(r0w + i * 16) * MLD + kk * 8], MLD);
            #pragma unroll
            for (int j = 0; j < 4; j++) {
                wmma::load_matrix_sync(bv[j], &sV[(j * 16) * MLD + kk * 8], MLD);
                wmma::load_matrix_sync(bs[j], &sS[(j * 16) * MLD + kk * 8], MLD);
            }
            #pragma unroll
            for (int i = 0; i < 2; i++)
                #pragma unroll
                for (int j = 0; j < 4; j++) {
                    wmma::mma_sync(vf[i][j], af[i], bv[j], vf[i][j]);
                    wmma::mma_sync(yf[i][j], af[i], bs[j], yf[i][j]);
                }
        }
        #pragma unroll
        for (int i = 0; i < 2; i++)
            #pragma unroll
            for (int j = 0; j < 4; j++)
                for (int e = 0; e < vf[i][j].num_elements; e++) {
                    vf[i][j].x[e] = clip3(vf[i][j].x[e]);
                    yf[i][j].x[e] = clip3(yf[i][j].x[e]);
                }
        // y_pred -> sA (nodes are dead)
        #pragma unroll
        for (int i = 0; i < 2; i++)
            #pragma unroll
            for (int j = 0; j < 4; j++)
                wmma::store_matrix_sync(&sA[(r0w + i * 16) * MLD + j * 16], yf[i][j], MLD, wmma::mem_row_major);
        __syncthreads();    // all warps done reading agg (sB)
        // v -> sB
        #pragma unroll
        for (int i = 0; i < 2; i++)
            #pragma unroll
            for (int j = 0; j < 4; j++)
                wmma::store_matrix_sync(&sB[(r0w + i * 16) * MLD + j * 16], vf[i][j], MLD, wmma::mem_row_major);
    }
    __syncthreads();

    // mix = sigmoid(v . mix_w + mix_b); convert y_pred (sA) to tf32 in place
    {
        int n = t;
        float m = mix_b[0];
        #pragma unroll
        for (int d = 0; d < DD; d++) m += sB[n * MLD + d] * smw[d];
        smix[n] = sigmoidf_(m);
        float* ya = &sA[n * MLD];
        #pragma unroll
        for (int d = 0; d < DD; d++) ya[d] = wmma::__float_to_tf32(ya[d]);
    }
    __syncthreads();

    // v_pred = clip(y_pred @ V^T) -> sA
    {
        CFrag pf[2][4];
        #pragma unroll
        for (int i = 0; i < 2; i++)
            #pragma unroll
            for (int j = 0; j < 4; j++) wmma::fill_fragment(pf[i][j], 0.f);
        #pragma unroll
        for (int kk = 0; kk < 8; kk++) {
            AFrag af[2]; BFrag bv[4];
            #pragma unroll
            for (int i = 0; i < 2; i++) wmma::load_matrix_sync(af[i], &sA[(r0w + i * 16) * MLD + kk * 8], MLD);
            #pragma unroll
            for (int j = 0; j < 4; j++) wmma::load_matrix_sync(bv[j], &sV[(j * 16) * MLD + kk * 8], MLD);
            #pragma unroll
            for (int i = 0; i < 2; i++)
                #pragma unroll
                for (int j = 0; j < 4; j++) wmma::mma_sync(pf[i][j], af[i], bv[j], pf[i][j]);
        }
        #pragma unroll
        for (int i = 0; i < 2; i++)
            #pragma unroll
            for (int j = 0; j < 4; j++)
                for (int e = 0; e < pf[i][j].num_elements; e++) pf[i][j].x[e] = clip3(pf[i][j].x[e]);
        __syncthreads();    // all reads of sA done
        #pragma unroll
        for (int i = 0; i < 2; i++)
            #pragma unroll
            for (int j = 0; j < 4; j++)
                wmma::store_matrix_sync(&sA[(r0w + i * 16) * MLD + j * 16], pf[i][j], MLD, wmma::mem_row_major);
    }
    __syncthreads();

    // cell_out = clip(mix*v + (1-mix)*v_pred) -> sA (tf32)
    {
        int n = t;
        float m = smix[n];
        float* va = &sB[n * MLD];
        float* pa = &sA[n * MLD];
        #pragma unroll
        for (int d = 0; d < DD; d++)
            pa[d] = wmma::__float_to_tf32(clip3(m * va[d] + (1.f - m) * pa[d]));
    }
    __syncthreads();

    // Q = cell_out @ q_w^T -> sB (bias added in next stage)
    {
        CFrag qf[2][4];
        #pragma unroll
        for (int i = 0; i < 2; i++)
            #pragma unroll
            for (int j = 0; j < 4; j++) wmma::fill_fragment(qf[i][j], 0.f);
        #pragma unroll
        for (int kk = 0; kk < 8; kk++) {
            AFrag af[2]; BFrag bq[4];
            #pragma unroll
            for (int i = 0; i < 2; i++) wmma::load_matrix_sync(af[i], &sA[(r0w + i * 16) * MLD + kk * 8], MLD);
            #pragma unroll
            for (int j = 0; j < 4; j++) wmma::load_matrix_sync(bq[j], &sQm[(j * 16) * MLD + kk * 8], MLD);
            #pragma unroll
            for (int i = 0; i < 2; i++)
                #pragma unroll
                for (int j = 0; j < 4; j++) wmma::mma_sync(qf[i][j], af[i], bq[j], qf[i][j]);
        }
        #pragma unroll
        for (int i = 0; i < 2; i++)
            #pragma unroll
            for (int j = 0; j < 4; j++)
                wmma::store_matrix_sync(&sB[(r0w + i * 16) * MLD + j * 16], qf[i][j], MLD, wmma::mem_row_major);
    }
    __syncthreads();

    // attention over 4 basis vectors + softmax + x_clean -> sA
    {
        int n = t;
        float q[DD];
        #pragma unroll
        for (int d = 0; d < DD; d++) q[d] = sB[n * MLD + d] + sqb[d];
        float s0 = 0.f, s1 = 0.f, s2 = 0.f, s3 = 0.f;
        #pragma unroll
        for (int d = 0; d < DD; d++) {
            s0 += q[d] * sKb[d];        s1 += q[d] * sKb[64 + d];
            s2 += q[d] * sKb[128 + d];  s3 += q[d] * sKb[192 + d];
        }
        s0 *= 0.125f; s1 *= 0.125f; s2 *= 0.125f; s3 *= 0.125f;
        float mx = fmaxf(fmaxf(s0, s1), fmaxf(s2, s3));
        float e0 = expf(s0 - mx), e1 = expf(s1 - mx), e2 = expf(s2 - mx), e3 = expf(s3 - mx);
        float inv = 1.f / (e0 + e1 + e2 + e3);
        e0 *= inv; e1 *= inv; e2 *= inv; e3 *= inv;
        float* dst = &sA[n * MLD];
        #pragma unroll
        for (int d = 0; d < DD; d++)
            dst[d] = clip3(e0 * sBas[d] + e1 * sBas[64 + d] + e2 * sBas[128 + d] + e3 * sBas[192 + d]);
    }
    __syncthreads();

    // coalesced writeback
    {
        float4* op = (float4*)(g_xclean + (size_t)b * HH);
        for (int i = t; i < HH / 4; i += 256) {
            int n = i >> 4, d = (i & 15) << 2;
            op[i] = *(float4*)&sA[n * MLD + d];
        }
    }
}

// ---------------- output bias epilogue --------------------------------------
__global__ void bias_out_kernel(const float* __restrict__ b_out, float* __restrict__ out)
{
    int idx = blockIdx.x * blockDim.x + threadIdx.x;
    if (idx < BB * CC) {
        int bb = idx / CC, c = idx - bb * CC;
        out[idx] = g_logits[(size_t)bb * CPAD + c] + b_out[c];
    }
}

// ---------------- launcher ---------------------------------------------------
extern "C" void kernel_launch(void* const* d_in, const int* in_sizes, int n_in,
                              void* d_out, int out_size)
{
    (void)in_sizes; (void)n_in; (void)out_size;
    const float* x      = (const float*)d_in[0];
    const float* W_in   = (const float*)d_in[1];
    const float* b_in   = (const float*)d_in[2];
    const float* adj_w  = (const float*)d_in[3];
    /* d_in[4] adj_mask: structurally implied by the 16x16 grid */
    const float* V_slow = (const float*)d_in[5];
    const float* sem    = (const float*)d_in[6];
    const float* mix_w  = (const float*)d_in[7];
    const float* mix_b  = (const float*)d_in[8];
    const float* basis  = (const float*)d_in[9];
    const float* q_w    = (const float*)d_in[10];
    const float* q_b    = (const float*)d_in[11];
    const float* k_w    = (const float*)d_in[12];
    const float* k_b    = (const float*)d_in[13];
    const float* W_out  = (const float*)d_in[14];
    const float* b_out  = (const float*)d_in[15];
    float* out = (float*)d_out;

    cudaFuncSetAttribute(middle_kernel, cudaFuncAttributeMaxDynamicSharedMemorySize, MID_SMEM_BYTES);

    void *p_nodes = 0, *p_xclean = 0, *p_logits = 0;
    cudaGetSymbolAddress(&p_nodes,  g_nodes);
    cudaGetSymbolAddress(&p_xclean, g_xclean);
    cudaGetSymbolAddress(&p_logits, g_logits);

    prep_kernel<<<1, 256>>>(adj_w, k_w, k_b, basis);

    // nodes = x @ W_in^T   (input bias folded into middle kernel)
    gemm_nt_tf32<<<dim3(HH / BN, BB / BM), 256>>>(x, W_in, (float*)p_nodes, BB, HH, FF, HH);

    middle_kernel<<<BB, 256, MID_SMEM_BYTES>>>(b_in, V_slow, sem, mix_w, mix_b, basis, q_w, q_b);

    // logits_pad = x_clean @ W_out^T
    gemm_nt_tf32<<<dim3(CPAD / BN, BB / BM), 256>>>((const float*)p_xclean, W_out, (float*)p_logits,
                                                    BB, CC, HH, CPAD);

    bias_out_kernel<<<(BB * CC + 255) / 256, 256>>>(b_out, out);
}

// round 2
// speedup vs baseline: 2.6366x; 2.6366x over previous
#include <cuda_runtime.h>
#include <mma.h>
#include <math.h>

using namespace nvcuda;

#define GRIDN 16
#define NN 256
#define DD 64
#define BB 4096
#define FF 512
#define HH 16384
#define CC 1000
#define CPAD 1024

// ---------------- scratch ----------------------------------------------------
__device__ float g_nodes[(size_t)BB * HH];     // 256 MB
__device__ float g_w[(size_t)BB * CPAD];       // 16.8 MB  (softmax weights, 4/node)
__device__ float g_mmat[(size_t)CPAD * CPAD];  // 4 MB     (folded basis x W_out)
__device__ float g_logits[(size_t)BB * CPAD];  // 16.8 MB
__device__ float g_adjw[NN * 4];
__device__ int   g_adjn[NN * 4];
__device__ float g_K[4 * DD];

__device__ __forceinline__ float sigmoidf_(float x) { return 1.0f / (1.0f + expf(-x)); }
__device__ __forceinline__ float clip3(float x) { return fminf(fmaxf(x, -3.0f), 3.0f); }

// ---------------- prep: adjacency rows + K = basis @ k_w^T + k_b ------------
__global__ void prep_kernel(const float* __restrict__ adjw,
                            const float* __restrict__ k_w,
                            const float* __restrict__ k_b,
                            const float* __restrict__ basis)
{
    int t = threadIdx.x;
    int r = t >> 4, c = t & 15;
    int nb[4]; int cnt = 0;
    if (r > 0)         nb[cnt++] = t - GRIDN;
    if (r < GRIDN - 1) nb[cnt++] = t + GRIDN;
    if (c > 0)         nb[cnt++] = t - 1;
    if (c < GRIDN - 1) nb[cnt++] = t + 1;

    float w[4] = {0.f, 0.f, 0.f, 0.f};
    float deg = 0.f;
    for (int j = 0; j < cnt; j++) { w[j] = sigmoidf_(adjw[t * NN + nb[j]]); deg += w[j]; }
    deg = fmaxf(deg, 1e-6f);
    int over = 0;
    for (int j = 0; j < cnt; j++) { w[j] /= deg; if (w[j] > 0.1f) over++; }
    if (over < 1) w[0] = fmaxf(w[0], 0.5f);
    for (int j = 0; j < 4; j++) {
        g_adjw[t * 4 + j] = (j < cnt) ? w[j] : 0.f;
        g_adjn[t * 4 + j] = (j < cnt) ? nb[j] : t;
    }

    int kr = t >> 6, kc = t & 63;
    float acc = k_b[kc];
    for (int d = 0; d < DD; d++) acc += basis[kr * DD + d] * k_w[kc * DD + d];
    g_K[kr * DD + kc] = acc;
}

// ---------------- Mmat[c, n*4+j] = sum_d basis[j,d] * W_out[c, n*64+d] ------
__global__ void mmat_kernel(const float* __restrict__ W_out, const float* __restrict__ basis)
{
    int gw = (blockIdx.x * blockDim.x + threadIdx.x) >> 5;   // row = c*256+n
    int lane = threadIdx.x & 31;
    if (gw >= CC * NN) return;
    const float* row = W_out + (size_t)gw * DD;
    float v0 = row[lane], v1 = row[lane + 32];
    float r0 = v0 * basis[       lane] + v1 * basis[       lane + 32];
    float r1 = v0 * basis[ 64 +  lane] + v1 * basis[ 64 +  lane + 32];
    float r2 = v0 * basis[128 +  lane] + v1 * basis[128 +  lane + 32];
    float r3 = v0 * basis[192 +  lane] + v1 * basis[192 +  lane + 32];
    #pragma unroll
    for (int o = 16; o; o >>= 1) {
        r0 += __shfl_xor_sync(0xffffffffu, r0, o);
        r1 += __shfl_xor_sync(0xffffffffu, r1, o);
        r2 += __shfl_xor_sync(0xffffffffu, r2, o);
        r3 += __shfl_xor_sync(0xffffffffu, r3, o);
    }
    if (lane == 0) ((float4*)g_mmat)[gw] = make_float4(r0, r1, r2, r3);
}

// ---------------- pipelined NT GEMM (tf32, cp.async 3-stage) ----------------
#define BM 128
#define BN 128
#define BK 32
#define GLDS 36
#define GSTAGE 3
#define GSTRIDE ((BM + BN) * GLDS)                 // 9216 floats / stage
#define GEMM_SMEM (GSTAGE * GSTRIDE * 4)           // 110592 B

__device__ __forceinline__ void g_issue(const float* A, const float* B, float* sm,
                                        int t, int m0, int n0, int K, int Nvalid,
                                        int kt, int s)
{
    int k0 = kt * BK;
    float* dstA0 = sm + s * GSTRIDE;
    float* dstB0 = dstA0 + BM * GLDS;
    #pragma unroll
    for (int i = 0; i < 4; i++) {
        int id = t + i * 256;
        int row = id >> 3, c4 = id & 7;
        const float* gA = A + (size_t)(m0 + row) * K + k0 + c4 * 4;
        unsigned int da = (unsigned int)__cvta_generic_to_shared(dstA0 + row * GLDS + c4 * 4);
        asm volatile("cp.async.cg.shared.global [%0], [%1], 16;\n" :: "r"(da), "l"(gA));
        int brow = n0 + row;
        const float* gB = B + (size_t)brow * K + k0 + c4 * 4;
        unsigned int db = (unsigned int)__cvta_generic_to_shared(dstB0 + row * GLDS + c4 * 4);
        int sz = (brow < Nvalid) ? 16 : 0;
        asm volatile("cp.async.cg.shared.global [%0], [%1], 16, %2;\n" :: "r"(db), "l"(gB), "r"(sz));
    }
    asm volatile("cp.async.commit_group;\n" ::: "memory");
}

__global__ __launch_bounds__(256, 2) void gemm_nt_pipe(
    const float* __restrict__ A, const float* __restrict__ B, float* __restrict__ C,
    int M, int Nvalid, int K, int ldc)
{
    extern __shared__ float sm[];
    int t = threadIdx.x;
    int m0 = blockIdx.y * BM, n0 = blockIdx.x * BN;
    int w = t >> 5, wm = w & 1, wn = w >> 1;
    int KT = K / BK;

    wmma::fragment<wmma::accumulator, 16, 16, 8, float> acc[4][2];
    #pragma unroll
    for (int i = 0; i < 4; i++)
        #pragma unroll
        for (int j = 0; j < 2; j++) wmma::fill_fragment(acc[i][j], 0.0f);

    g_issue(A, B, sm, t, m0, n0, K, Nvalid, 0, 0);
    g_issue(A, B, sm, t, m0, n0, K, Nvalid, 1, 1);

    for (int kt = 0; kt < KT; kt++) {
        asm volatile("cp.async.wait_group 1;\n" ::: "memory");
        __syncthreads();
        if (kt + 2 < KT)
            g_issue(A, B, sm, t, m0, n0, K, Nvalid, kt + 2, (kt + 2) % GSTAGE);

        const float* sa = sm + (kt % GSTAGE) * GSTRIDE;
        const float* sb = sa + BM * GLDS;
        #pragma unroll
        for (int kk = 0; kk < BK / 8; kk++) {
            wmma::fragment<wmma::matrix_a, 16, 16, 8, wmma::precision::tf32, wmma::row_major> af[4];
            wmma::fragment<wmma::matrix_b, 16, 16, 8, wmma::precision::tf32, wmma::col_major> bf[2];
            #pragma unroll
            for (int i = 0; i < 4; i++) {
                wmma::load_matrix_sync(af[i], sa + (wm * 64 + i * 16) * GLDS + kk * 8, GLDS);
                #pragma unroll
                for (int e = 0; e < af[i].num_elements; e++)
                    af[i].x[e] = wmma::__float_to_tf32(af[i].x[e]);
            }
            #pragma unroll
            for (int j = 0; j < 2; j++) {
                wmma::load_matrix_sync(bf[j], sb + (wn * 32 + j * 16) * GLDS + kk * 8, GLDS);
                #pragma unroll
                for (int e = 0; e < bf[j].num_elements; e++)
                    bf[j].x[e] = wmma::__float_to_tf32(bf[j].x[e]);
            }
            #pragma unroll
            for (int i = 0; i < 4; i++)
                #pragma unroll
                for (int j = 0; j < 2; j++)
                    wmma::mma_sync(acc[i][j], af[i], bf[j], acc[i][j]);
        }
    }
    #pragma unroll
    for (int i = 0; i < 4; i++)
        #pragma unroll
        for (int j = 0; j < 2; j++)
            wmma::store_matrix_sync(C + (size_t)(m0 + wm * 64 + i * 16) * ldc + n0 + wn * 32 + j * 16,
                                    acc[i][j], ldc, wmma::mem_row_major);
}

// ---------------- fused middle: one CTA per batch element -------------------
#define MLD 68
constexpr int MID_SMEM_FLOATS = 256 * MLD * 2 + 64 * MLD * 3 + 256 + 1024 + 256 + 64 + 64 + 1024;
constexpr int MID_SMEM_BYTES  = MID_SMEM_FLOATS * 4;

__global__ __launch_bounds__(256) void middle_kernel(
    const float* __restrict__ b_in, const float* __restrict__ V_slow,
    const float* __restrict__ sem_mem, const float* __restrict__ mix_w,
    const float* __restrict__ mix_b, const float* __restrict__ q_w,
    const float* __restrict__ q_b)
{
    extern __shared__ float smem_[];
    float* sA   = smem_;               // 256*68
    float* sB   = sA + 256 * MLD;      // 256*68
    float* sV   = sB + 256 * MLD;      // 64*68
    float* sS   = sV + 64 * MLD;       // 64*68
    float* sQm  = sS + 64 * MLD;       // 64*68
    float* smix = sQm + 64 * MLD;      // 256
    float* sw4  = smix + 256;          // 1024
    float* sKb  = sw4 + 1024;          // 256
    float* sqb  = sKb + 256;           // 64
    float* smw  = sqb + 64;            // 64
    int*   sn4  = (int*)(smw + 64);    // 1024

    int b = blockIdx.x;
    int t = threadIdx.x;

    for (int i = t; i < 64 * 64; i += 256) {
        int r = i >> 6, c2 = i & 63;
        sV[r * MLD + c2]  = wmma::__float_to_tf32(V_slow[i]);
        sS[r * MLD + c2]  = wmma::__float_to_tf32(sem_mem[i]);
        sQm[r * MLD + c2] = wmma::__float_to_tf32(q_w[i]);
    }
    if (t < 64) { sqb[t] = q_b[t]; smw[t] = mix_w[t]; }
    sKb[t] = g_K[t];
    #pragma unroll
    for (int j = 0; j < 4; j++) { sw4[t * 4 + j] = g_adjw[t * 4 + j]; sn4[t * 4 + j] = g_adjn[t * 4 + j]; }

    // nodes + input bias -> sA
    {
        const float4* np_ = (const float4*)(g_nodes + (size_t)b * HH);
        const float4* bp_ = (const float4*)b_in;
        for (int i = t; i < HH / 4; i += 256) {
            float4 v = np_[i], bb = bp_[i];
            int n = i >> 4, d = (i & 15) << 2;
            float* dst = &sA[n * MLD + d];
            dst[0] = v.x + bb.x; dst[1] = v.y + bb.y; dst[2] = v.z + bb.z; dst[3] = v.w + bb.w;
        }
    }
    __syncthreads();

    // sparse message passing -> sB (tf32)
    {
        int n = t;
        float w0 = sw4[n * 4 + 0], w1 = sw4[n * 4 + 1], w2 = sw4[n * 4 + 2], w3 = sw4[n * 4 + 3];
        const float* r0 = &sA[sn4[n * 4 + 0] * MLD];
        const float* r1 = &sA[sn4[n * 4 + 1] * MLD];
        const float* r2 = &sA[sn4[n * 4 + 2] * MLD];
        const float* r3 = &sA[sn4[n * 4 + 3] * MLD];
        float* dst = &sB[n * MLD];
        #pragma unroll
        for (int d = 0; d < DD; d++)
            dst[d] = wmma::__float_to_tf32(w0 * r0[d] + w1 * r1[d] + w2 * r2[d] + w3 * r3[d]);
    }
    __syncthreads();

    int w = t >> 5;
    int r0w = w * 32;

    typedef wmma::fragment<wmma::matrix_a, 16, 16, 8, wmma::precision::tf32, wmma::row_major> AFrag;
    typedef wmma::fragment<wmma::matrix_b, 16, 16, 8, wmma::precision::tf32, wmma::col_major> BFrag;
    typedef wmma::fragment<wmma::accumulator, 16, 16, 8, float> CFrag;

    // v = clip(agg @ V^T), y_pred = clip(agg @ S^T)
    {
        CFrag vf[2][4], yf[2][4];
        #pragma unroll
        for (int i = 0; i < 2; i++)
            #pragma unroll
            for (int j = 0; j < 4; j++) { wmma::fill_fragment(vf[i][j], 0.f); wmma::fill_fragment(yf[i][j], 0.f); }
        #pragma unroll
        for (int kk = 0; kk < 8; kk++) {
            AFrag af[2]; BFrag bv[4], bs[4];
            #pragma unroll
            for (int i = 0; i < 2; i++) wmma::load_matrix_sync(af[i], &sB[(r0w + i * 16) * MLD + kk * 8], MLD);
            #pragma unroll
            for (int j = 0; j < 4; j++) {
                wmma::load_matrix_sync(bv[j], &sV[(j * 16) * MLD + kk * 8], MLD);
                wmma::load_matrix_sync(bs[j], &sS[(j * 16) * MLD + kk * 8], MLD);
            }
            #pragma unroll
            for (int i = 0; i < 2; i++)
                #pragma unroll
                for (int j = 0; j < 4; j++) {
                    wmma::mma_sync(vf[i][j], af[i], bv[j], vf[i][j]);
                    wmma::mma_sync(yf[i][j], af[i], bs[j], yf[i][j]);
                }
        }
        #pragma unroll
        for (int i = 0; i < 2; i++)
            #pragma unroll
            for (int j = 0; j < 4; j++)
                for (int e = 0; e < vf[i][j].num_elements; e++) {
                    vf[i][j].x[e] = clip3(vf[i][j].x[e]);
                    yf[i][j].x[e] = clip3(yf[i][j].x[e]);
                }
        #pragma unroll
        for (int i = 0; i < 2; i++)
            #pragma unroll
            for (int j = 0; j < 4; j++)
                wmma::store_matrix_sync(&sA[(r0w + i * 16) * MLD + j * 16], yf[i][j], MLD, wmma::mem_row_major);
        __syncthreads();
        #pragma unroll
        for (int i = 0; i < 2; i++)
            #pragma unroll
            for (int j = 0; j < 4; j++)
                wmma::store_matrix_sync(&sB[(r0w + i * 16) * MLD + j * 16], vf[i][j], MLD, wmma::mem_row_major);
    }
    __syncthreads();

    // mix = sigmoid(v . mix_w + mix_b); y_pred -> tf32 in place
    {
        int n = t;
        float m = mix_b[0];
        #pragma unroll
        for (int d = 0; d < DD; d++) m += sB[n * MLD + d] * smw[d];
        smix[n] = sigmoidf_(m);
        float* ya = &sA[n * MLD];
        #pragma unroll
        for (int d = 0; d < DD; d++) ya[d] = wmma::__float_to_tf32(ya[d]);
    }
    __syncthreads();

    // v_pred = clip(y_pred @ V^T) -> sA
    {
        CFrag pf[2][4];
        #pragma unroll
        for (int i = 0; i < 2; i++)
            #pragma unroll
            for (int j = 0; j < 4; j++) wmma::fill_fragment(pf[i][j], 0.f);
        #pragma unroll
        for (int kk = 0; kk < 8; kk++) {
            AFrag af[2]; BFrag bv[4];
            #pragma unroll
            for (int i = 0; i < 2; i++) wmma::load_matrix_sync(af[i], &sA[(r0w + i * 16) * MLD + kk * 8], MLD);
            #pragma unroll
            for (int j = 0; j < 4; j++) wmma::load_matrix_sync(bv[j], &sV[(j * 16) * MLD + kk * 8], MLD);
            #pragma unroll
            for (int i = 0; i < 2; i++)
                #pragma unroll
                for (int j = 0; j < 4; j++) wmma::mma_sync(pf[i][j], af[i], bv[j], pf[i][j]);
        }
        #pragma unroll
        for (int i = 0; i < 2; i++)
            #pragma unroll
            for (int j = 0; j < 4; j++)
                for (int e = 0; e < pf[i][j].num_elements; e++) pf[i][j].x[e] = clip3(pf[i][j].x[e]);
        __syncthreads();
        #pragma unroll
        for (int i = 0; i < 2; i++)
            #pragma unroll
            for (int j = 0; j < 4; j++)
                wmma::store_matrix_sync(&sA[(r0w + i * 16) * MLD + j * 16], pf[i][j], MLD, wmma::mem_row_major);
    }
    __syncthreads();

    // cell_out = clip(mix*v + (1-mix)*v_pred) -> sA (tf32)
    {
        int n = t;
        float m = smix[n];
        float* va = &sB[n * MLD];
        float* pa = &sA[n * MLD];
        #pragma unroll
        for (int d = 0; d < DD; d++)
            pa[d] = wmma::__float_to_tf32(clip3(m * va[d] + (1.f - m) * pa[d]));
    }
    __syncthreads();

    // Q = cell_out @ q_w^T -> sB
    {
        CFrag qf[2][4];
        #pragma unroll
        for (int i = 0; i < 2; i++)
            #pragma unroll
            for (int j = 0; j < 4; j++) wmma::fill_fragment(qf[i][j], 0.f);
        #pragma unroll
        for (int kk = 0; kk < 8; kk++) {
            AFrag af[2]; BFrag bq[4];
            #pragma unroll
            for (int i = 0; i < 2; i++) wmma::load_matrix_sync(af[i], &sA[(r0w + i * 16) * MLD + kk * 8], MLD);
            #pragma unroll
            for (int j = 0; j < 4; j++) wmma::load_matrix_sync(bq[j], &sQm[(j * 16) * MLD + kk * 8], MLD);
            #pragma unroll
            for (int i = 0; i < 2; i++)
                #pragma unroll
                for (int j = 0; j < 4; j++) wmma::mma_sync(qf[i][j], af[i], bq[j], qf[i][j]);
        }
        #pragma unroll
        for (int i = 0; i < 2; i++)
            #pragma unroll
            for (int j = 0; j < 4; j++)
                wmma::store_matrix_sync(&sB[(r0w + i * 16) * MLD + j * 16], qf[i][j], MLD, wmma::mem_row_major);
    }
    __syncthreads();

    // attention over 4 basis vectors -> softmax weights -> g_w
    {
        int n = t;
        float q[DD];
        #pragma unroll
        for (int d = 0; d < DD; d++) q[d] = sB[n * MLD + d] + sqb[d];
        float s0 = 0.f, s1 = 0.f, s2 = 0.f, s3 = 0.f;
        #pragma unroll
        for (int d = 0; d < DD; d++) {
            s0 += q[d] * sKb[d];        s1 += q[d] * sKb[64 + d];
            s2 += q[d] * sKb[128 + d];  s3 += q[d] * sKb[192 + d];
        }
        s0 *= 0.125f; s1 *= 0.125f; s2 *= 0.125f; s3 *= 0.125f;
        float mx = fmaxf(fmaxf(s0, s1), fmaxf(s2, s3));
        float e0 = expf(s0 - mx), e1 = expf(s1 - mx), e2 = expf(s2 - mx), e3 = expf(s3 - mx);
        float inv = 1.f / (e0 + e1 + e2 + e3);
        ((float4*)(g_w + (size_t)b * CPAD))[n] = make_float4(e0 * inv, e1 * inv, e2 * inv, e3 * inv);
    }
}

// ---------------- output bias epilogue --------------------------------------
__global__ void bias_out_kernel(const float* __restrict__ b_out, float* __restrict__ out)
{
    int idx = blockIdx.x * blockDim.x + threadIdx.x;
    if (idx < BB * CC) {
        int bb = idx / CC, c = idx - bb * CC;
        out[idx] = g_logits[(size_t)bb * CPAD + c] + b_out[c];
    }
}

// ---------------- launcher ---------------------------------------------------
extern "C" void kernel_launch(void* const* d_in, const int* in_sizes, int n_in,
                              void* d_out, int out_size)
{
    (void)in_sizes; (void)n_in; (void)out_size;
    const float* x      = (const float*)d_in[0];
    const float* W_in   = (const float*)d_in[1];
    const float* b_in   = (const float*)d_in[2];
    const float* adj_w  = (const float*)d_in[3];
    const float* V_slow = (const float*)d_in[5];
    const float* sem    = (const float*)d_in[6];
    const float* mix_w  = (const float*)d_in[7];
    const float* mix_b  = (const float*)d_in[8];
    const float* basis  = (const float*)d_in[9];
    const float* q_w    = (const float*)d_in[10];
    const float* q_b    = (const float*)d_in[11];
    const float* k_w    = (const float*)d_in[12];
    const float* k_b    = (const float*)d_in[13];
    const float* W_out  = (const float*)d_in[14];
    const float* b_out  = (const float*)d_in[15];
    float* out = (float*)d_out;

    cudaFuncSetAttribute(gemm_nt_pipe, cudaFuncAttributeMaxDynamicSharedMemorySize, GEMM_SMEM);
    cudaFuncSetAttribute(middle_kernel, cudaFuncAttributeMaxDynamicSharedMemorySize, MID_SMEM_BYTES);

    void *p_nodes = 0, *p_w = 0, *p_mmat = 0, *p_logits = 0;
    cudaGetSymbolAddress(&p_nodes,  g_nodes);
    cudaGetSymbolAddress(&p_w,      g_w);
    cudaGetSymbolAddress(&p_mmat,   g_mmat);
    cudaGetSymbolAddress(&p_logits, g_logits);

    prep_kernel<<<1, 256>>>(adj_w, k_w, k_b, basis);
    mmat_kernel<<<(CC * NN) / 8, 256>>>(W_out, basis);

    // nodes = x @ W_in^T
    gemm_nt_pipe<<<dim3(HH / BN, BB / BM), 256, GEMM_SMEM>>>(x, W_in, (float*)p_nodes, BB, HH, FF, HH);

    middle_kernel<<<BB, 256, MID_SMEM_BYTES>>>(b_in, V_slow, sem, mix_w, mix_b, q_w, q_b);

    // logits_pad = w @ Mmat^T
    gemm_nt_pipe<<<dim3(CPAD / BN, BB / BM), 256, GEMM_SMEM>>>((const float*)p_w, (const float*)p_mmat,
                                                               (float*)p_logits, BB, CC, CPAD, CPAD);

    bias_out_kernel<<<(BB * CC + 255) / 256, 256>>>(b_out, out);
}